// round 13
// baseline (speedup 1.0000x reference)
#include <cuda_runtime.h>
#include <cuda_bf16.h>
#include <math.h>
#include <stdint.h>

// Problem constants
#define BQ   512
#define KT   64
#define EBD  256
#define VFD  512
#define SENS 768
#define H0   512
#define H1   256
#define H2   64
#define C0   1280
#define C1   768
#define C2   320

// ---------------- device scratch (static, no allocation) ----------------
__device__ __align__(16) __nv_bfloat16 Xh[(size_t)BQ * KT * SENS];
__device__ __align__(16) __nv_bfloat16 Xl[(size_t)BQ * KT * SENS];
__device__ __align__(16) __nv_bfloat16 W0h[(size_t)4 * H0 * C0];
__device__ __align__(16) __nv_bfloat16 W0l[(size_t)4 * H0 * C0];
__device__ __align__(16) __nv_bfloat16 W1h[(size_t)4 * H1 * C1];
__device__ __align__(16) __nv_bfloat16 W1l[(size_t)4 * H1 * C1];
__device__ __align__(16) __nv_bfloat16 W2h[(size_t)4 * H2 * C2];
__device__ __align__(16) __nv_bfloat16 W2l[(size_t)4 * H2 * C2];
__device__ __align__(16) __nv_bfloat16 h0h[2][BQ * H0];
__device__ __align__(16) __nv_bfloat16 h0l[2][BQ * H0];
__device__ __align__(16) __nv_bfloat16 h1h[2][BQ * H1];
__device__ __align__(16) __nv_bfloat16 h1l[2][BQ * H1];
__device__ __align__(16) __nv_bfloat16 h2h[2][BQ * H2];
__device__ __align__(16) __nv_bfloat16 h2l[2][BQ * H2];

// ---------------- helpers ----------------
__device__ __forceinline__ void bf16_split(float v, __nv_bfloat16& hi, __nv_bfloat16& lo)
{
    hi = __float2bfloat16(v);
    lo = __float2bfloat16(v - __bfloat162float(hi));
}

__device__ __forceinline__ void mma_bf16(float* d, const uint32_t* a, const uint32_t* b)
{
    asm volatile(
        "mma.sync.aligned.m16n8k16.row.col.f32.bf16.bf16.f32 "
        "{%0,%1,%2,%3}, {%4,%5,%6,%7}, {%8,%9}, {%0,%1,%2,%3};\n"
        : "+f"(d[0]), "+f"(d[1]), "+f"(d[2]), "+f"(d[3])
        : "r"(a[0]), "r"(a[1]), "r"(a[2]), "r"(a[3]),
          "r"(b[0]), "r"(b[1]));
}

__device__ __forceinline__ void cpa16(uint32_t* dst_smem, const void* src_gmem)
{
    uint32_t d = (uint32_t)__cvta_generic_to_shared(dst_smem);
    asm volatile("cp.async.cg.shared.global [%0], [%1], 16;\n" :: "r"(d), "l"(src_gmem));
}

#define LDSM4(r0, r1, r2, r3, a) \
    asm volatile("ldmatrix.sync.aligned.m8n8.x4.shared.b16 {%0,%1,%2,%3}, [%4];" \
                 : "=r"(r0), "=r"(r1), "=r"(r2), "=r"(r3) : "r"(a))

// ---------------- prep kernels ----------------
__global__ void prep_weights_bf(const float* __restrict__ ff1, const float* __restrict__ ff2,
                                const float* __restrict__ ta,  const float* __restrict__ tb,
                                const float* __restrict__ mask,
                                __nv_bfloat16* __restrict__ dh, __nv_bfloat16* __restrict__ dl,
                                int hid, int cat)
{
    int idx = blockIdx.x * blockDim.x + threadIdx.x;
    if (idx >= hid * cat) return;
    int j = idx / cat;
    int k = idx - j * cat;
    float m = mask[idx];
    float v[4] = { ff1[idx] * m, ff2[idx] * m, ta[idx], tb[idx] };
    #pragma unroll
    for (int q = 0; q < 4; q++) {
        __nv_bfloat16 hi, lo;
        bf16_split(v[q], hi, lo);
        size_t o = (size_t)(4 * j + q) * cat + k;
        dh[o] = hi; dl[o] = lo;
    }
}

__global__ void prep_inputs_bf(const float* __restrict__ base, const float* __restrict__ vis,
                               __nv_bfloat16* __restrict__ xh, __nv_bfloat16* __restrict__ xl)
{
    size_t idx = (size_t)blockIdx.x * blockDim.x + threadIdx.x;
    if (idx >= (size_t)BQ * KT * SENS) return;
    size_t row = idx / SENS;
    int c = (int)(idx - row * SENS);
    float v = (c < EBD) ? base[row * EBD + c] : vis[row * VFD + (c - EBD)];
    __nv_bfloat16 hi, lo;
    bf16_split(v, hi, lo);
    xh[idx] = hi; xl[idx] = lo;
}

__global__ void extract_out(const __nv_bfloat16* __restrict__ hh,
                            const __nv_bfloat16* __restrict__ hl,
                            float* __restrict__ out, int n)
{
    int i = blockIdx.x * blockDim.x + threadIdx.x;
    if (i < n) out[i] = __bfloat162float(hh[i]) + __bfloat162float(hl[i]);
}

// ---------------- fused GEMM tile (3xBF16, m16n8k16, ldmatrix) + CfC epilogue ----------------
// 256 threads = 8 warps as 4(M) x 2(N). Block tile BM x BN of
// C[M, 4*hid] = X[M, cat] @ W[cat, 4*hid] (W stored [4*hid][cat], k contig).
// acc += Ahi*Bhi + Ahi*Blo + Alo*Bhi.
template<int BM, int BN>
__device__ void cfc_tile(uint32_t* sm32,
                         int bx, int by,
                         const __nv_bfloat16* __restrict__ s0h, const __nv_bfloat16* __restrict__ s0l,
                         int st0, int len0,
                         const __nv_bfloat16* __restrict__ s1h, const __nv_bfloat16* __restrict__ s1l,
                         int st1,
                         const __nv_bfloat16* __restrict__ Wh, const __nv_bfloat16* __restrict__ Wl,
                         const float* __restrict__ bff1, const float* __restrict__ bff2,
                         const float* __restrict__ bta,  const float* __restrict__ btb,
                         int cat, int hid,
                         __nv_bfloat16* __restrict__ oh, __nv_bfloat16* __restrict__ ol)
{
    constexpr int RS   = 20;             // row stride in u32 (40 bf16) - conflict-free
    constexpr int TWM  = BM / 4;         // 4 warps along M
    constexpr int TWN  = BN / 2;         // 2 warps along N
    constexpr int MT   = TWM / 16;
    constexpr int NT   = TWN / 8;        // 8
    constexpr int APL  = BM * RS;        // A plane size (u32)
    constexpr int BPL  = BN * RS;
    constexpr int BUFSZ = 2 * APL + 2 * BPL;

    const int tid  = threadIdx.x;
    const int lane = tid & 31;
    const int wid  = tid >> 5;
    const int wm   = wid & 3;            // 0..3 along M
    const int wn   = wid >> 2;           // 0..1 along N
    const int g    = lane >> 2;
    const int tc   = lane & 3;

    const int rowBase = bx * BM;
    const int colBase = by * BN;
    const int l0 = len0;

    // ldmatrix per-lane address components (bytes)
    const uint32_t smemB = (uint32_t)__cvta_generic_to_shared(sm32);
    const int aLaneRow = (lane & 7) + ((lane >> 3) & 1) * 8;
    const int aKoff    = ((lane >> 4) & 1) * 16;
    const int bLaneRow = (lane & 7) + ((lane >> 4) & 1) * 8;
    const int bKoff    = ((lane >> 3) & 1) * 16;
    const uint32_t aBaseOff = (uint32_t)((wm * TWM + aLaneRow) * (RS * 4) + aKoff);
    const uint32_t bBaseOff = (uint32_t)((wn * TWN + bLaneRow) * (RS * 4) + bKoff);

    float acc[MT][NT][4];
    #pragma unroll
    for (int i = 0; i < MT; i++)
        #pragma unroll
        for (int q = 0; q < NT; q++)
            #pragma unroll
            for (int z = 0; z < 4; z++) acc[i][q][z] = 0.0f;

    auto load_tiles = [&](int k0, int buf) {
        const __nv_bfloat16 *shi, *slo; int ss, so;
        if (k0 < l0) { shi = s0h; slo = s0l; ss = st0; so = k0; }
        else         { shi = s1h; slo = s1l; ss = st1; so = k0 - l0; }
        uint32_t* bb = sm32 + buf * BUFSZ;
        #pragma unroll
        for (int i = 0; i < BM * 4 / 256; i++) {        // A: BM rows x 4 chunks
            int idx = tid + i * 256;
            int r = idx >> 2, c = idx & 3;
            size_t go = (size_t)(rowBase + r) * ss + so + c * 8;
            cpa16(bb + r * RS + c * 4, shi + go);
            cpa16(bb + APL + r * RS + c * 4, slo + go);
        }
        #pragma unroll
        for (int i = 0; i < BN * 4 / 256; i++) {        // B: BN rows x 4 chunks
            int idx = tid + i * 256;
            int r = idx >> 2, c = idx & 3;
            size_t go = (size_t)(colBase + r) * cat + k0 + c * 8;
            cpa16(bb + 2 * APL + r * RS + c * 4, Wh + go);
            cpa16(bb + 2 * APL + BPL + r * RS + c * 4, Wl + go);
        }
        asm volatile("cp.async.commit_group;\n");
    };

    load_tiles(0, 0);

    const int ntile = cat / 32;
    int buf = 0;
    for (int it = 0; it < ntile; it++, buf ^= 1) {
        if (it + 1 < ntile) {
            load_tiles((it + 1) * 32, buf ^ 1);
            asm volatile("cp.async.wait_group 1;\n");
        } else {
            asm volatile("cp.async.wait_group 0;\n");
        }
        __syncthreads();

        const uint32_t bufB = smemB + (uint32_t)(buf * BUFSZ) * 4;
        const uint32_t aHi = bufB + aBaseOff;
        const uint32_t aLo = bufB + (uint32_t)APL * 4 + aBaseOff;
        const uint32_t bHi = bufB + (uint32_t)(2 * APL) * 4 + bBaseOff;
        const uint32_t bLo = bufB + (uint32_t)(2 * APL + BPL) * 4 + bBaseOff;

        #pragma unroll
        for (int k16 = 0; k16 < 2; k16++) {
            const uint32_t ko = (uint32_t)(k16 * 32);
            uint32_t ah[MT][4], al[MT][4];
            #pragma unroll
            for (int mt = 0; mt < MT; mt++) {
                LDSM4(ah[mt][0], ah[mt][1], ah[mt][2], ah[mt][3], aHi + mt * 16 * (RS * 4) + ko);
                LDSM4(al[mt][0], al[mt][1], al[mt][2], al[mt][3], aLo + mt * 16 * (RS * 4) + ko);
            }
            uint32_t bh[NT][2], bl[NT][2];
            #pragma unroll
            for (int p = 0; p < NT / 2; p++) {
                LDSM4(bh[2 * p][0], bh[2 * p][1], bh[2 * p + 1][0], bh[2 * p + 1][1],
                      bHi + p * 16 * (RS * 4) + ko);
                LDSM4(bl[2 * p][0], bl[2 * p][1], bl[2 * p + 1][0], bl[2 * p + 1][1],
                      bLo + p * 16 * (RS * 4) + ko);
            }
            #pragma unroll
            for (int mt = 0; mt < MT; mt++)
                #pragma unroll
                for (int nt = 0; nt < NT; nt++)
                    mma_bf16(acc[mt][nt], ah[mt], bh[nt]);
            #pragma unroll
            for (int mt = 0; mt < MT; mt++)
                #pragma unroll
                for (int nt = 0; nt < NT; nt++)
                    mma_bf16(acc[mt][nt], ah[mt], bl[nt]);
            #pragma unroll
            for (int mt = 0; mt < MT; mt++)
                #pragma unroll
                for (int nt = 0; nt < NT; nt++)
                    mma_bf16(acc[mt][nt], al[mt], bh[nt]);
        }
        __syncthreads();
    }

    // ---------------- CfC epilogue ----------------
    // Even lanes hold (ff1,ff2), odd lanes (ta,tb) of the same neuron.
    #pragma unroll
    for (int nt = 0; nt < NT; nt++) {
        const int cb = colBase + wn * TWN + nt * 8;
        const int j  = (cb >> 2) + (tc >> 1);
        const float bf1 = bff1[j], bf2 = bff2[j], bt1 = bta[j], bt2 = btb[j];
        #pragma unroll
        for (int mt = 0; mt < MT; mt++) {
            const int r = rowBase + wm * TWM + mt * 16 + g;
            float d0 = acc[mt][nt][0], d1 = acc[mt][nt][1];
            float d2 = acc[mt][nt][2], d3 = acc[mt][nt][3];
            float o0 = __shfl_xor_sync(0xffffffffu, d0, 1);
            float o1 = __shfl_xor_sync(0xffffffffu, d1, 1);
            float o2 = __shfl_xor_sync(0xffffffffu, d2, 1);
            float o3 = __shfl_xor_sync(0xffffffffu, d3, 1);
            if (!(lane & 1)) {
                {
                    float f1 = tanhf(d0 + bf1);
                    float f2 = tanhf(d1 + bf2);
                    float s  = (o0 + bt1) + (o1 + bt2);
                    float ti = 1.0f / (1.0f + expf(-s));
                    float v  = f1 + ti * (f2 - f1);
                    __nv_bfloat16 hi, lo; bf16_split(v, hi, lo);
                    oh[(size_t)r * hid + j] = hi;
                    ol[(size_t)r * hid + j] = lo;
                }
                {
                    float f1 = tanhf(d2 + bf1);
                    float f2 = tanhf(d3 + bf2);
                    float s  = (o2 + bt1) + (o3 + bt2);
                    float ti = 1.0f / (1.0f + expf(-s));
                    float v  = f1 + ti * (f2 - f1);
                    __nv_bfloat16 hi, lo; bf16_split(v, hi, lo);
                    oh[(size_t)(r + 8) * hid + j] = hi;
                    ol[(size_t)(r + 8) * hid + j] = lo;
                }
            }
        }
    }
}

// ---------------- merged pipeline-slot kernel ----------------
// Slot s: blocks [0,64)  = L0(t=s)   tiles 128x128 over C 512x2048
//         [64,128)       = L1(t=s-1) tiles  64x128 over C 512x1024
//         [128,144)      = L2(t=s-2) tiles  64x128 over C 512x256
// Ping-pong safety (within one launch):
//   L0(s) writes h0[(s+1)&1]; L1(s-1) reads h0[s&1]
//   L1(s-1) writes h1[s&1];   L2(s-2) reads h1[(s-1)&1]
__global__ __launch_bounds__(256)
void fused_step(int s,
                const float* __restrict__ b0f1, const float* __restrict__ b0f2,
                const float* __restrict__ b0ta, const float* __restrict__ b0tb,
                const float* __restrict__ b1f1, const float* __restrict__ b1f2,
                const float* __restrict__ b1ta, const float* __restrict__ b1tb,
                const float* __restrict__ b2f1, const float* __restrict__ b2f2,
                const float* __restrict__ b2ta, const float* __restrict__ b2tb)
{
    extern __shared__ __align__(16) uint32_t sm32[];
    int b = blockIdx.x;
    if (b < 64) {
        int t = s;
        if (t >= KT) return;
        int pi = t & 1, po = pi ^ 1;
        cfc_tile<128, 128>(sm32, b & 3, b >> 2,
                           Xh + (size_t)t * SENS, Xl + (size_t)t * SENS, KT * SENS, SENS,
                           h0h[pi], h0l[pi], H0,
                           W0h, W0l, b0f1, b0f2, b0ta, b0tb,
                           C0, H0, h0h[po], h0l[po]);
    } else if (b < 128) {
        int t = s - 1;
        if (t < 0 || t >= KT) return;
        int pi = t & 1, po = pi ^ 1;
        b -= 64;
        cfc_tile<64, 128>(sm32, b & 7, b >> 3,
                          h0h[po], h0l[po], H0, H0,
                          h1h[pi], h1l[pi], H1,
                          W1h, W1l, b1f1, b1f2, b1ta, b1tb,
                          C1, H1, h1h[po], h1l[po]);
    } else {
        int t = s - 2;
        if (t < 0 || t >= KT) return;
        int pi = t & 1, po = pi ^ 1;
        b -= 128;
        cfc_tile<64, 128>(sm32, b & 7, b >> 3,
                          h1h[po], h1l[po], H1, H1,
                          h2h[pi], h2l[pi], H2,
                          W2h, W2l, b2f1, b2f2, b2ta, b2tb,
                          C2, H2, h2h[po], h2l[po]);
    }
}

// dynamic smem: <128,128> path: 2 buf x (2*128 + 2*128) rows x 80 B = 81920
#define SMF 81920

// ---------------- host launcher ----------------
extern "C" void kernel_launch(void* const* d_in, const int* in_sizes, int n_in,
                              void* d_out, int out_size)
{
    const float* base = (const float*)d_in[0];
    const float* vis  = (const float*)d_in[1];
    const float* w[3][9];
    for (int li = 0; li < 3; li++)
        for (int q = 0; q < 9; q++)
            w[li][q] = (const float*)d_in[2 + li * 9 + q];

    __nv_bfloat16 *pXh, *pXl, *pW0h, *pW0l, *pW1h, *pW1l, *pW2h, *pW2l;
    __nv_bfloat16 *p0h, *p0l, *p1h, *p1l, *p2h, *p2l;
    cudaGetSymbolAddress((void**)&pXh, Xh);   cudaGetSymbolAddress((void**)&pXl, Xl);
    cudaGetSymbolAddress((void**)&pW0h, W0h); cudaGetSymbolAddress((void**)&pW0l, W0l);
    cudaGetSymbolAddress((void**)&pW1h, W1h); cudaGetSymbolAddress((void**)&pW1l, W1l);
    cudaGetSymbolAddress((void**)&pW2h, W2h); cudaGetSymbolAddress((void**)&pW2l, W2l);
    cudaGetSymbolAddress((void**)&p0h, h0h);  cudaGetSymbolAddress((void**)&p0l, h0l);
    cudaGetSymbolAddress((void**)&p1h, h1h);  cudaGetSymbolAddress((void**)&p1l, h1l);
    cudaGetSymbolAddress((void**)&p2h, h2h);  cudaGetSymbolAddress((void**)&p2l, h2l);

    cudaFuncSetAttribute((const void*)fused_step,
                         cudaFuncAttributeMaxDynamicSharedMemorySize, SMF);

    // zero initial hidden states (ping buffer 0)
    cudaMemsetAsync(p0h, 0, (size_t)BQ * H0 * sizeof(__nv_bfloat16));
    cudaMemsetAsync(p0l, 0, (size_t)BQ * H0 * sizeof(__nv_bfloat16));
    cudaMemsetAsync(p1h, 0, (size_t)BQ * H1 * sizeof(__nv_bfloat16));
    cudaMemsetAsync(p1l, 0, (size_t)BQ * H1 * sizeof(__nv_bfloat16));
    cudaMemsetAsync(p2h, 0, (size_t)BQ * H2 * sizeof(__nv_bfloat16));
    cudaMemsetAsync(p2l, 0, (size_t)BQ * H2 * sizeof(__nv_bfloat16));

    // prep
    {
        size_t n = (size_t)BQ * KT * SENS;
        prep_inputs_bf<<<(unsigned)((n + 255) / 256), 256>>>(base, vis, pXh, pXl);
    }
    prep_weights_bf<<<(H0 * C0 + 255) / 256, 256>>>(w[0][0], w[0][2], w[0][4], w[0][6], w[0][8], pW0h, pW0l, H0, C0);
    prep_weights_bf<<<(H1 * C1 + 255) / 256, 256>>>(w[1][0], w[1][2], w[1][4], w[1][6], w[1][8], pW1h, pW1l, H1, C1);
    prep_weights_bf<<<(H2 * C2 + 255) / 256, 256>>>(w[2][0], w[2][2], w[2][4], w[2][6], w[2][8], pW2h, pW2l, H2, C2);

    // pipeline: slot s runs L0(s) || L1(s-1) || L2(s-2)
    for (int s = 0; s < KT + 2; s++) {
        fused_step<<<144, 256, SMF>>>(s,
            w[0][1], w[0][3], w[0][5], w[0][7],
            w[1][1], w[1][3], w[1][5], w[1][7],
            w[2][1], w[2][3], w[2][5], w[2][7]);
    }

    // final motor-layer state: L2(KT-1) wrote slot 0
    extract_out<<<(BQ * H2 + 255) / 256, 256>>>(p2h, p2l, (float*)d_out, BQ * H2);
}

// round 14
// speedup vs baseline: 1.5531x; 1.5531x over previous
#include <cuda_runtime.h>
#include <cuda_bf16.h>
#include <math.h>
#include <stdint.h>

// Problem constants
#define BQ   512
#define KT   64
#define EBD  256
#define VFD  512
#define SENS 768
#define H0   512
#define H1   256
#define H2   64
#define C0   1280
#define C1   768
#define C2   320

// ---------------- device scratch (static, no allocation) ----------------
__device__ __align__(16) __nv_bfloat16 Xh[(size_t)BQ * KT * SENS];
__device__ __align__(16) __nv_bfloat16 Xl[(size_t)BQ * KT * SENS];
// Weights: [3*hid][cat] rows interleaved {ff1, ff2, ta+tb}, k contiguous.
__device__ __align__(16) __nv_bfloat16 W0h[(size_t)3 * H0 * C0];
__device__ __align__(16) __nv_bfloat16 W0l[(size_t)3 * H0 * C0];
__device__ __align__(16) __nv_bfloat16 W1h[(size_t)3 * H1 * C1];
__device__ __align__(16) __nv_bfloat16 W1l[(size_t)3 * H1 * C1];
__device__ __align__(16) __nv_bfloat16 W2h[(size_t)3 * H2 * C2];
__device__ __align__(16) __nv_bfloat16 W2l[(size_t)3 * H2 * C2];
__device__ __align__(16) __nv_bfloat16 h0h[2][BQ * H0];
__device__ __align__(16) __nv_bfloat16 h0l[2][BQ * H0];
__device__ __align__(16) __nv_bfloat16 h1h[2][BQ * H1];
__device__ __align__(16) __nv_bfloat16 h1l[2][BQ * H1];
__device__ __align__(16) __nv_bfloat16 h2h[2][BQ * H2];
__device__ __align__(16) __nv_bfloat16 h2l[2][BQ * H2];

// ---------------- helpers ----------------
__device__ __forceinline__ void bf16_split(float v, __nv_bfloat16& hi, __nv_bfloat16& lo)
{
    hi = __float2bfloat16(v);
    lo = __float2bfloat16(v - __bfloat162float(hi));
}

__device__ __forceinline__ void mma_bf16(float* d, const uint32_t* a, const uint32_t* b)
{
    asm volatile(
        "mma.sync.aligned.m16n8k16.row.col.f32.bf16.bf16.f32 "
        "{%0,%1,%2,%3}, {%4,%5,%6,%7}, {%8,%9}, {%0,%1,%2,%3};\n"
        : "+f"(d[0]), "+f"(d[1]), "+f"(d[2]), "+f"(d[3])
        : "r"(a[0]), "r"(a[1]), "r"(a[2]), "r"(a[3]),
          "r"(b[0]), "r"(b[1]));
}

__device__ __forceinline__ void cpa16(uint32_t* dst_smem, const void* src_gmem)
{
    uint32_t d = (uint32_t)__cvta_generic_to_shared(dst_smem);
    asm volatile("cp.async.cg.shared.global [%0], [%1], 16;\n" :: "r"(d), "l"(src_gmem));
}

#define LDSM4(r0, r1, r2, r3, a) \
    asm volatile("ldmatrix.sync.aligned.m8n8.x4.shared.b16 {%0,%1,%2,%3}, [%4];" \
                 : "=r"(r0), "=r"(r1), "=r"(r2), "=r"(r3) : "r"(a))

// ---------------- prep kernels ----------------
// W3[3j+q][k], q in {ff1, ff2, ta+tb}; mask folded into ff1/ff2.
__global__ void prep_weights3(const float* __restrict__ ff1, const float* __restrict__ ff2,
                              const float* __restrict__ ta,  const float* __restrict__ tb,
                              const float* __restrict__ mask,
                              __nv_bfloat16* __restrict__ dh, __nv_bfloat16* __restrict__ dl,
                              int hid, int cat)
{
    int idx = blockIdx.x * blockDim.x + threadIdx.x;
    if (idx >= hid * cat) return;
    int j = idx / cat;
    int k = idx - j * cat;
    float m = mask[idx];
    float v[3] = { ff1[idx] * m, ff2[idx] * m, ta[idx] + tb[idx] };
    #pragma unroll
    for (int q = 0; q < 3; q++) {
        __nv_bfloat16 hi, lo;
        bf16_split(v[q], hi, lo);
        size_t o = (size_t)(3 * j + q) * cat + k;
        dh[o] = hi; dl[o] = lo;
    }
}

__global__ void prep_inputs_bf(const float* __restrict__ base, const float* __restrict__ vis,
                               __nv_bfloat16* __restrict__ xh, __nv_bfloat16* __restrict__ xl)
{
    size_t idx = (size_t)blockIdx.x * blockDim.x + threadIdx.x;
    if (idx >= (size_t)BQ * KT * SENS) return;
    size_t row = idx / SENS;
    int c = (int)(idx - row * SENS);
    float v = (c < EBD) ? base[row * EBD + c] : vis[row * VFD + (c - EBD)];
    __nv_bfloat16 hi, lo;
    bf16_split(v, hi, lo);
    xh[idx] = hi; xl[idx] = lo;
}

__global__ void extract_out(const __nv_bfloat16* __restrict__ hh,
                            const __nv_bfloat16* __restrict__ hl,
                            float* __restrict__ out, int n)
{
    int i = blockIdx.x * blockDim.x + threadIdx.x;
    if (i < n) out[i] = __bfloat162float(hh[i]) + __bfloat162float(hl[i]);
}

// ---------------- fused GEMM tile (3xBF16, m16n8k16) + CfC epilogue ----------------
// Fixed tile 64(M) x 96(N) of C[M, 3*hid] = X[M, cat] @ W3[cat, 3*hid].
// 256 threads = 8 warps as 4(M) x 2(N): warp tile 16 x 48 (MT=1, NT=6).
// acc += Ahi*Bhi + Ahi*Blo + Alo*Bhi.  Epilogue stages fp32 C to smem, then
// each thread combines the 3 comps {ff1,ff2,ts} of a neuron.
__device__ void cfc_tile(uint32_t* sm32,
                         int bx, int by,
                         const __nv_bfloat16* __restrict__ s0h, const __nv_bfloat16* __restrict__ s0l,
                         int st0, int len0,
                         const __nv_bfloat16* __restrict__ s1h, const __nv_bfloat16* __restrict__ s1l,
                         int st1,
                         const __nv_bfloat16* __restrict__ Wh, const __nv_bfloat16* __restrict__ Wl,
                         const float* __restrict__ bff1, const float* __restrict__ bff2,
                         const float* __restrict__ bta,  const float* __restrict__ btb,
                         int cat, int hid,
                         __nv_bfloat16* __restrict__ oh, __nv_bfloat16* __restrict__ ol)
{
    constexpr int BM   = 64;
    constexpr int BN   = 96;
    constexpr int RS   = 20;             // row stride in u32 (40 bf16) - conflict-free
    constexpr int NT   = 6;
    constexpr int APL  = BM * RS;        // 1280 u32
    constexpr int BPL  = BN * RS;        // 1920 u32
    constexpr int BUFSZ = 2 * APL + 2 * BPL;  // 6400 u32

    const int tid  = threadIdx.x;
    const int lane = tid & 31;
    const int wid  = tid >> 5;
    const int wm   = wid & 3;            // 0..3 along M (16 rows each)
    const int wn   = wid >> 2;           // 0..1 along N (48 cols each)
    const int g    = lane >> 2;
    const int tc   = lane & 3;

    const int rowBase = bx * BM;
    const int colBase = by * BN;
    const int l0 = len0;

    const uint32_t smemB = (uint32_t)__cvta_generic_to_shared(sm32);
    const int aLaneRow = (lane & 7) + ((lane >> 3) & 1) * 8;
    const int aKoff    = ((lane >> 4) & 1) * 16;
    const int bLaneRow = (lane & 7) + ((lane >> 4) & 1) * 8;
    const int bKoff    = ((lane >> 3) & 1) * 16;
    const uint32_t aBaseOff = (uint32_t)((wm * 16 + aLaneRow) * (RS * 4) + aKoff);
    const uint32_t bBaseOff = (uint32_t)((wn * 48 + bLaneRow) * (RS * 4) + bKoff);

    float acc[NT][4];
    #pragma unroll
    for (int q = 0; q < NT; q++)
        #pragma unroll
        for (int z = 0; z < 4; z++) acc[q][z] = 0.0f;

    auto load_tiles = [&](int k0, int buf) {
        const __nv_bfloat16 *shi, *slo; int ss, so;
        if (k0 < l0) { shi = s0h; slo = s0l; ss = st0; so = k0; }
        else         { shi = s1h; slo = s1l; ss = st1; so = k0 - l0; }
        uint32_t* bb = sm32 + buf * BUFSZ;
        {   // A: 64 rows x 4 chunks = 256 (one per thread)
            int r = tid >> 2, c = tid & 3;
            size_t go = (size_t)(rowBase + r) * ss + so + c * 8;
            cpa16(bb + r * RS + c * 4, shi + go);
            cpa16(bb + APL + r * RS + c * 4, slo + go);
        }
        #pragma unroll
        for (int i = 0; i < 2; i++) {   // B: 96 rows x 4 chunks = 384
            int idx = tid + i * 256;
            if (idx < BN * 4) {
                int r = idx >> 2, c = idx & 3;
                size_t go = (size_t)(colBase + r) * cat + k0 + c * 8;
                cpa16(bb + 2 * APL + r * RS + c * 4, Wh + go);
                cpa16(bb + 2 * APL + BPL + r * RS + c * 4, Wl + go);
            }
        }
        asm volatile("cp.async.commit_group;\n");
    };

    load_tiles(0, 0);

    const int ntile = cat / 32;
    int buf = 0;
    for (int it = 0; it < ntile; it++, buf ^= 1) {
        if (it + 1 < ntile) {
            load_tiles((it + 1) * 32, buf ^ 1);
            asm volatile("cp.async.wait_group 1;\n");
        } else {
            asm volatile("cp.async.wait_group 0;\n");
        }
        __syncthreads();

        const uint32_t bufB = smemB + (uint32_t)(buf * BUFSZ) * 4;
        const uint32_t aHi = bufB + aBaseOff;
        const uint32_t aLo = bufB + (uint32_t)APL * 4 + aBaseOff;
        const uint32_t bHi = bufB + (uint32_t)(2 * APL) * 4 + bBaseOff;
        const uint32_t bLo = bufB + (uint32_t)(2 * APL + BPL) * 4 + bBaseOff;

        #pragma unroll
        for (int k16 = 0; k16 < 2; k16++) {
            const uint32_t ko = (uint32_t)(k16 * 32);
            uint32_t ah[4], al[4];
            LDSM4(ah[0], ah[1], ah[2], ah[3], aHi + ko);
            LDSM4(al[0], al[1], al[2], al[3], aLo + ko);
            uint32_t bh[NT][2], bl[NT][2];
            #pragma unroll
            for (int p = 0; p < NT / 2; p++) {
                LDSM4(bh[2 * p][0], bh[2 * p][1], bh[2 * p + 1][0], bh[2 * p + 1][1],
                      bHi + p * 16 * (RS * 4) + ko);
                LDSM4(bl[2 * p][0], bl[2 * p][1], bl[2 * p + 1][0], bl[2 * p + 1][1],
                      bLo + p * 16 * (RS * 4) + ko);
            }
            #pragma unroll
            for (int nt = 0; nt < NT; nt++)
                mma_bf16(acc[nt], ah, bh[nt]);
            #pragma unroll
            for (int nt = 0; nt < NT; nt++)
                mma_bf16(acc[nt], ah, bl[nt]);
            #pragma unroll
            for (int nt = 0; nt < NT; nt++)
                mma_bf16(acc[nt], al, bh[nt]);
        }
        __syncthreads();
    }
    // all warps past the final sync: smem buffers free for staging

    // ---------------- stage fp32 C tile to smem ----------------
    constexpr int CS = 100;              // Cs row stride (floats)
    float* Cs = reinterpret_cast<float*>(sm32);
    {
        const int r0 = wm * 16 + g;
        const int cb = wn * 48 + 2 * tc;
        #pragma unroll
        for (int nt = 0; nt < NT; nt++) {
            const int c = cb + nt * 8;
            *reinterpret_cast<float2*>(&Cs[r0 * CS + c])       = make_float2(acc[nt][0], acc[nt][1]);
            *reinterpret_cast<float2*>(&Cs[(r0 + 8) * CS + c]) = make_float2(acc[nt][2], acc[nt][3]);
        }
    }
    __syncthreads();

    // ---------------- CfC epilogue: 64 rows x 32 neurons ----------------
    const int jBase = colBase / 3;       // colBase multiple of 96 -> multiple of 32
    #pragma unroll
    for (int i = 0; i < 8; i++) {
        int o  = tid + i * 256;          // 0..2047
        int r  = o >> 5;                 // 0..63
        int jj = o & 31;                 // neuron within tile
        float c0 = Cs[r * CS + 3 * jj + 0];
        float c1 = Cs[r * CS + 3 * jj + 1];
        float c2 = Cs[r * CS + 3 * jj + 2];
        int j = jBase + jj;
        float f1 = tanhf(c0 + bff1[j]);
        float f2 = tanhf(c1 + bff2[j]);
        float s  = c2 + bta[j] + btb[j];
        float ti = 1.0f / (1.0f + expf(-s));
        float v  = f1 + ti * (f2 - f1);
        __nv_bfloat16 hi, lo; bf16_split(v, hi, lo);
        oh[(size_t)(rowBase + r) * hid + j] = hi;
        ol[(size_t)(rowBase + r) * hid + j] = lo;
    }
}

// ---------------- merged pipeline-slot kernel ----------------
// Slot s: blocks [0,128)   = L0(t=s)   tiles 64x96 over C 512x1536
//         [128,192)        = L1(t=s-1) tiles 64x96 over C 512x768
//         [192,208)        = L2(t=s-2) tiles 64x96 over C 512x192
// Ping-pong safety (within one launch):
//   L0(s) writes h0[(s+1)&1]; L1(s-1) reads h0[s&1]
//   L1(s-1) writes h1[s&1];   L2(s-2) reads h1[(s-1)&1]
__global__ __launch_bounds__(256)
void fused_step(int s,
                const float* __restrict__ b0f1, const float* __restrict__ b0f2,
                const float* __restrict__ b0ta, const float* __restrict__ b0tb,
                const float* __restrict__ b1f1, const float* __restrict__ b1f2,
                const float* __restrict__ b1ta, const float* __restrict__ b1tb,
                const float* __restrict__ b2f1, const float* __restrict__ b2f2,
                const float* __restrict__ b2ta, const float* __restrict__ b2tb)
{
    extern __shared__ __align__(16) uint32_t sm32[];
    int b = blockIdx.x;
    if (b < 128) {
        int t = s;
        if (t >= KT) return;
        int pi = t & 1, po = pi ^ 1;
        cfc_tile(sm32, b & 7, b >> 3,
                 Xh + (size_t)t * SENS, Xl + (size_t)t * SENS, KT * SENS, SENS,
                 h0h[pi], h0l[pi], H0,
                 W0h, W0l, b0f1, b0f2, b0ta, b0tb,
                 C0, H0, h0h[po], h0l[po]);
    } else if (b < 192) {
        int t = s - 1;
        if (t < 0 || t >= KT) return;
        int pi = t & 1, po = pi ^ 1;
        b -= 128;
        cfc_tile(sm32, b & 7, b >> 3,
                 h0h[po], h0l[po], H0, H0,
                 h1h[pi], h1l[pi], H1,
                 W1h, W1l, b1f1, b1f2, b1ta, b1tb,
                 C1, H1, h1h[po], h1l[po]);
    } else {
        int t = s - 2;
        if (t < 0 || t >= KT) return;
        int pi = t & 1, po = pi ^ 1;
        b -= 192;
        cfc_tile(sm32, b & 7, b >> 3,
                 h1h[po], h1l[po], H1, H1,
                 h2h[pi], h2l[pi], H2,
                 W2h, W2l, b2f1, b2f2, b2ta, b2tb,
                 C2, H2, h2h[po], h2l[po]);
    }
}

// dynamic smem: 2 buf x 6400 u32 x 4 B = 51200 (>= Cs staging 64*100*4 = 25600)
#define SMF 51200

// ---------------- host launcher ----------------
extern "C" void kernel_launch(void* const* d_in, const int* in_sizes, int n_in,
                              void* d_out, int out_size)
{
    const float* base = (const float*)d_in[0];
    const float* vis  = (const float*)d_in[1];
    const float* w[3][9];
    for (int li = 0; li < 3; li++)
        for (int q = 0; q < 9; q++)
            w[li][q] = (const float*)d_in[2 + li * 9 + q];

    __nv_bfloat16 *pXh, *pXl, *pW0h, *pW0l, *pW1h, *pW1l, *pW2h, *pW2l;
    __nv_bfloat16 *p0h, *p0l, *p1h, *p1l, *p2h, *p2l;
    cudaGetSymbolAddress((void**)&pXh, Xh);   cudaGetSymbolAddress((void**)&pXl, Xl);
    cudaGetSymbolAddress((void**)&pW0h, W0h); cudaGetSymbolAddress((void**)&pW0l, W0l);
    cudaGetSymbolAddress((void**)&pW1h, W1h); cudaGetSymbolAddress((void**)&pW1l, W1l);
    cudaGetSymbolAddress((void**)&pW2h, W2h); cudaGetSymbolAddress((void**)&pW2l, W2l);
    cudaGetSymbolAddress((void**)&p0h, h0h);  cudaGetSymbolAddress((void**)&p0l, h0l);
    cudaGetSymbolAddress((void**)&p1h, h1h);  cudaGetSymbolAddress((void**)&p1l, h1l);
    cudaGetSymbolAddress((void**)&p2h, h2h);  cudaGetSymbolAddress((void**)&p2l, h2l);

    cudaFuncSetAttribute((const void*)fused_step,
                         cudaFuncAttributeMaxDynamicSharedMemorySize, SMF);

    // zero initial hidden states (ping buffer 0)
    cudaMemsetAsync(p0h, 0, (size_t)BQ * H0 * sizeof(__nv_bfloat16));
    cudaMemsetAsync(p0l, 0, (size_t)BQ * H0 * sizeof(__nv_bfloat16));
    cudaMemsetAsync(p1h, 0, (size_t)BQ * H1 * sizeof(__nv_bfloat16));
    cudaMemsetAsync(p1l, 0, (size_t)BQ * H1 * sizeof(__nv_bfloat16));
    cudaMemsetAsync(p2h, 0, (size_t)BQ * H2 * sizeof(__nv_bfloat16));
    cudaMemsetAsync(p2l, 0, (size_t)BQ * H2 * sizeof(__nv_bfloat16));

    // prep
    {
        size_t n = (size_t)BQ * KT * SENS;
        prep_inputs_bf<<<(unsigned)((n + 255) / 256), 256>>>(base, vis, pXh, pXl);
    }
    prep_weights3<<<(H0 * C0 + 255) / 256, 256>>>(w[0][0], w[0][2], w[0][4], w[0][6], w[0][8], pW0h, pW0l, H0, C0);
    prep_weights3<<<(H1 * C1 + 255) / 256, 256>>>(w[1][0], w[1][2], w[1][4], w[1][6], w[1][8], pW1h, pW1l, H1, C1);
    prep_weights3<<<(H2 * C2 + 255) / 256, 256>>>(w[2][0], w[2][2], w[2][4], w[2][6], w[2][8], pW2h, pW2l, H2, C2);

    // pipeline: slot s runs L0(s) || L1(s-1) || L2(s-2)
    for (int s = 0; s < KT + 2; s++) {
        fused_step<<<208, 256, SMF>>>(s,
            w[0][1], w[0][3], w[0][5], w[0][7],
            w[1][1], w[1][3], w[1][5], w[1][7],
            w[2][1], w[2][3], w[2][5], w[2][7]);
    }

    // final motor-layer state: L2(KT-1) wrote slot 0
    extract_out<<<(BQ * H2 + 255) / 256, 256>>>(p2h, p2l, (float*)d_out, BQ * H2);
}

// round 15
// speedup vs baseline: 1.5627x; 1.0062x over previous
#include <cuda_runtime.h>
#include <cuda_bf16.h>
#include <math.h>
#include <stdint.h>

// Problem constants
#define BQ   512
#define KT   64
#define EBD  256
#define VFD  512
#define SENS 768
#define H0   512
#define H1   256
#define H2   64
#define C0   1280
#define C1   768
#define C2   320

// queue geometry: 66 virtual slots x 416 items (L0:256, L1:128, L2:32)
#define QSLOT 416
#define QTOT  (66 * QSLOT)

// ---------------- device scratch (static, no allocation) ----------------
__device__ __align__(16) __nv_bfloat16 Xh[(size_t)BQ * KT * SENS];
__device__ __align__(16) __nv_bfloat16 Xl[(size_t)BQ * KT * SENS];
// Weights: [3*hid][cat] rows interleaved {ff1, ff2, ta+tb}, k contiguous.
__device__ __align__(16) __nv_bfloat16 W0h[(size_t)3 * H0 * C0];
__device__ __align__(16) __nv_bfloat16 W0l[(size_t)3 * H0 * C0];
__device__ __align__(16) __nv_bfloat16 W1h[(size_t)3 * H1 * C1];
__device__ __align__(16) __nv_bfloat16 W1l[(size_t)3 * H1 * C1];
__device__ __align__(16) __nv_bfloat16 W2h[(size_t)3 * H2 * C2];
__device__ __align__(16) __nv_bfloat16 W2l[(size_t)3 * H2 * C2];
__device__ __align__(16) __nv_bfloat16 h0h[2][BQ * H0];
__device__ __align__(16) __nv_bfloat16 h0l[2][BQ * H0];
__device__ __align__(16) __nv_bfloat16 h1h[2][BQ * H1];
__device__ __align__(16) __nv_bfloat16 h1l[2][BQ * H1];
__device__ __align__(16) __nv_bfloat16 h2h[2][BQ * H2];
__device__ __align__(16) __nv_bfloat16 h2l[2][BQ * H2];
// scheduler state
__device__ int qhead;
__device__ int cL0[KT * 16];
__device__ int cL1[KT * 16];
__device__ int cL2[KT * 16];

// ---------------- helpers ----------------
__device__ __forceinline__ void bf16_split(float v, __nv_bfloat16& hi, __nv_bfloat16& lo)
{
    hi = __float2bfloat16(v);
    lo = __float2bfloat16(v - __bfloat162float(hi));
}

__device__ __forceinline__ void mma_bf16(float* d, const uint32_t* a, const uint32_t* b)
{
    asm volatile(
        "mma.sync.aligned.m16n8k16.row.col.f32.bf16.bf16.f32 "
        "{%0,%1,%2,%3}, {%4,%5,%6,%7}, {%8,%9}, {%0,%1,%2,%3};\n"
        : "+f"(d[0]), "+f"(d[1]), "+f"(d[2]), "+f"(d[3])
        : "r"(a[0]), "r"(a[1]), "r"(a[2]), "r"(a[3]),
          "r"(b[0]), "r"(b[1]));
}

__device__ __forceinline__ void cpa16(uint32_t* dst_smem, const void* src_gmem)
{
    uint32_t d = (uint32_t)__cvta_generic_to_shared(dst_smem);
    asm volatile("cp.async.cg.shared.global [%0], [%1], 16;\n" :: "r"(d), "l"(src_gmem));
}

#define LDSM4(r0, r1, r2, r3, a) \
    asm volatile("ldmatrix.sync.aligned.m8n8.x4.shared.b16 {%0,%1,%2,%3}, [%4];" \
                 : "=r"(r0), "=r"(r1), "=r"(r2), "=r"(r3) : "r"(a))

__device__ __forceinline__ void wait_cnt(const int* p, int target)
{
    for (;;) {
        int v;
        asm volatile("ld.acquire.gpu.global.b32 %0, [%1];" : "=r"(v) : "l"(p));
        if (v >= target) break;
        __nanosleep(128);
    }
}

__device__ __forceinline__ void release_cnt(int* p)
{
    asm volatile("red.release.gpu.global.add.s32 [%0], 1;" :: "l"(p) : "memory");
}

// ---------------- prep kernels ----------------
__global__ void prep_sched()
{
    int i = blockIdx.x * blockDim.x + threadIdx.x;
    if (i == 0) qhead = 0;
    if (i < KT * 16) { cL0[i] = 0; cL1[i] = 0; cL2[i] = 0; }
}

// W3[3j+q][k], q in {ff1, ff2, ta+tb}; mask folded into ff1/ff2.
__global__ void prep_weights3(const float* __restrict__ ff1, const float* __restrict__ ff2,
                              const float* __restrict__ ta,  const float* __restrict__ tb,
                              const float* __restrict__ mask,
                              __nv_bfloat16* __restrict__ dh, __nv_bfloat16* __restrict__ dl,
                              int hid, int cat)
{
    int idx = blockIdx.x * blockDim.x + threadIdx.x;
    if (idx >= hid * cat) return;
    int j = idx / cat;
    int k = idx - j * cat;
    float m = mask[idx];
    float v[3] = { ff1[idx] * m, ff2[idx] * m, ta[idx] + tb[idx] };
    #pragma unroll
    for (int q = 0; q < 3; q++) {
        __nv_bfloat16 hi, lo;
        bf16_split(v[q], hi, lo);
        size_t o = (size_t)(3 * j + q) * cat + k;
        dh[o] = hi; dl[o] = lo;
    }
}

__global__ void prep_inputs_bf(const float* __restrict__ base, const float* __restrict__ vis,
                               __nv_bfloat16* __restrict__ xh, __nv_bfloat16* __restrict__ xl)
{
    size_t idx = (size_t)blockIdx.x * blockDim.x + threadIdx.x;
    if (idx >= (size_t)BQ * KT * SENS) return;
    size_t row = idx / SENS;
    int c = (int)(idx - row * SENS);
    float v = (c < EBD) ? base[row * EBD + c] : vis[row * VFD + (c - EBD)];
    __nv_bfloat16 hi, lo;
    bf16_split(v, hi, lo);
    xh[idx] = hi; xl[idx] = lo;
}

__global__ void extract_out(const __nv_bfloat16* __restrict__ hh,
                            const __nv_bfloat16* __restrict__ hl,
                            float* __restrict__ out, int n)
{
    int i = blockIdx.x * blockDim.x + threadIdx.x;
    if (i < n) out[i] = __bfloat162float(hh[i]) + __bfloat162float(hl[i]);
}

// ---------------- fused GEMM tile (3xBF16, m16n8k16) + CfC epilogue ----------------
// Fixed tile 32(M) x 96(N) of C[M, 3*hid] = X[M, cat] @ W3[cat, 3*hid].
// 128 threads = 4 warps as 2(M) x 2(N): warp tile 16 x 48 (NT=6).
// acc += Ahi*Bhi + Ahi*Blo + Alo*Bhi. Epilogue stages fp32 C via smem.
__device__ void cfc_tile(uint32_t* sm32,
                         int bx, int by,
                         const __nv_bfloat16* __restrict__ s0h, const __nv_bfloat16* __restrict__ s0l,
                         int st0, int len0,
                         const __nv_bfloat16* __restrict__ s1h, const __nv_bfloat16* __restrict__ s1l,
                         int st1,
                         const __nv_bfloat16* __restrict__ Wh, const __nv_bfloat16* __restrict__ Wl,
                         const float* __restrict__ bff1, const float* __restrict__ bff2,
                         const float* __restrict__ bts,
                         int cat, int hid,
                         __nv_bfloat16* __restrict__ oh, __nv_bfloat16* __restrict__ ol)
{
    constexpr int BM   = 32;
    constexpr int BN   = 96;
    constexpr int RS   = 20;             // row stride in u32 (40 bf16) - conflict-free
    constexpr int NT   = 6;
    constexpr int APL  = BM * RS;        // 640 u32
    constexpr int BPL  = BN * RS;        // 1920 u32
    constexpr int BUFSZ = 2 * APL + 2 * BPL;  // 5120 u32

    const int tid  = threadIdx.x;
    const int lane = tid & 31;
    const int wid  = tid >> 5;
    const int wm   = wid & 1;            // 0..1 along M (16 rows each)
    const int wn   = wid >> 1;           // 0..1 along N (48 cols each)
    const int g    = lane >> 2;
    const int tc   = lane & 3;

    const int rowBase = bx * BM;
    const int colBase = by * BN;
    const int l0 = len0;

    const uint32_t smemB = (uint32_t)__cvta_generic_to_shared(sm32);
    const int aLaneRow = (lane & 7) + ((lane >> 3) & 1) * 8;
    const int aKoff    = ((lane >> 4) & 1) * 16;
    const int bLaneRow = (lane & 7) + ((lane >> 4) & 1) * 8;
    const int bKoff    = ((lane >> 3) & 1) * 16;
    const uint32_t aBaseOff = (uint32_t)((wm * 16 + aLaneRow) * (RS * 4) + aKoff);
    const uint32_t bBaseOff = (uint32_t)((wn * 48 + bLaneRow) * (RS * 4) + bKoff);

    float acc[NT][4];
    #pragma unroll
    for (int q = 0; q < NT; q++)
        #pragma unroll
        for (int z = 0; z < 4; z++) acc[q][z] = 0.0f;

    auto load_tiles = [&](int k0, int buf) {
        const __nv_bfloat16 *shi, *slo; int ss, so;
        if (k0 < l0) { shi = s0h; slo = s0l; ss = st0; so = k0; }
        else         { shi = s1h; slo = s1l; ss = st1; so = k0 - l0; }
        uint32_t* bb = sm32 + buf * BUFSZ;
        {   // A: 32 rows x 4 chunks = 128 (one per thread)
            int r = tid >> 2, c = tid & 3;
            size_t go = (size_t)(rowBase + r) * ss + so + c * 8;
            cpa16(bb + r * RS + c * 4, shi + go);
            cpa16(bb + APL + r * RS + c * 4, slo + go);
        }
        #pragma unroll
        for (int i = 0; i < 3; i++) {   // B: 96 rows x 4 chunks = 384
            int idx = tid + i * 128;
            int r = idx >> 2, c = idx & 3;
            size_t go = (size_t)(colBase + r) * cat + k0 + c * 8;
            cpa16(bb + 2 * APL + r * RS + c * 4, Wh + go);
            cpa16(bb + 2 * APL + BPL + r * RS + c * 4, Wl + go);
        }
        asm volatile("cp.async.commit_group;\n");
    };

    load_tiles(0, 0);

    const int ntile = cat / 32;
    int buf = 0;
    for (int it = 0; it < ntile; it++, buf ^= 1) {
        if (it + 1 < ntile) {
            load_tiles((it + 1) * 32, buf ^ 1);
            asm volatile("cp.async.wait_group 1;\n");
        } else {
            asm volatile("cp.async.wait_group 0;\n");
        }
        __syncthreads();

        const uint32_t bufB = smemB + (uint32_t)(buf * BUFSZ) * 4;
        const uint32_t aHi = bufB + aBaseOff;
        const uint32_t aLo = bufB + (uint32_t)APL * 4 + aBaseOff;
        const uint32_t bHi = bufB + (uint32_t)(2 * APL) * 4 + bBaseOff;
        const uint32_t bLo = bufB + (uint32_t)(2 * APL + BPL) * 4 + bBaseOff;

        #pragma unroll
        for (int k16 = 0; k16 < 2; k16++) {
            const uint32_t ko = (uint32_t)(k16 * 32);
            uint32_t ah[4], al[4];
            LDSM4(ah[0], ah[1], ah[2], ah[3], aHi + ko);
            LDSM4(al[0], al[1], al[2], al[3], aLo + ko);
            uint32_t bh[NT][2], bl[NT][2];
            #pragma unroll
            for (int p = 0; p < NT / 2; p++) {
                LDSM4(bh[2 * p][0], bh[2 * p][1], bh[2 * p + 1][0], bh[2 * p + 1][1],
                      bHi + p * 16 * (RS * 4) + ko);
                LDSM4(bl[2 * p][0], bl[2 * p][1], bl[2 * p + 1][0], bl[2 * p + 1][1],
                      bLo + p * 16 * (RS * 4) + ko);
            }
            #pragma unroll
            for (int nt = 0; nt < NT; nt++)
                mma_bf16(acc[nt], ah, bh[nt]);
            #pragma unroll
            for (int nt = 0; nt < NT; nt++)
                mma_bf16(acc[nt], ah, bl[nt]);
            #pragma unroll
            for (int nt = 0; nt < NT; nt++)
                mma_bf16(acc[nt], al, bh[nt]);
        }
        __syncthreads();
    }
    // past final sync: smem buffers free for C staging

    constexpr int CS = 100;
    float* Cs = reinterpret_cast<float*>(sm32);
    {
        const int r0 = wm * 16 + g;
        const int cb = wn * 48 + 2 * tc;
        #pragma unroll
        for (int nt = 0; nt < NT; nt++) {
            const int c = cb + nt * 8;
            *reinterpret_cast<float2*>(&Cs[r0 * CS + c])       = make_float2(acc[nt][0], acc[nt][1]);
            *reinterpret_cast<float2*>(&Cs[(r0 + 8) * CS + c]) = make_float2(acc[nt][2], acc[nt][3]);
        }
    }
    __syncthreads();

    // CfC epilogue: 32 rows x 32 neurons
    const int jBase = colBase / 3;
    #pragma unroll
    for (int i = 0; i < 8; i++) {
        int o  = tid + i * 128;          // 0..1023
        int r  = o >> 5;                 // 0..31
        int jj = o & 31;
        float c0 = Cs[r * CS + 3 * jj + 0];
        float c1 = Cs[r * CS + 3 * jj + 1];
        float c2 = Cs[r * CS + 3 * jj + 2];
        int j = jBase + jj;
        float f1 = tanhf(c0 + bff1[j]);
        float f2 = tanhf(c1 + bff2[j]);
        float ti = 1.0f / (1.0f + expf(-(c2 + bts[j])));
        float v  = f1 + ti * (f2 - f1);
        __nv_bfloat16 hi, lo; bf16_split(v, hi, lo);
        oh[(size_t)(rowBase + r) * hid + j] = hi;
        ol[(size_t)(rowBase + r) * hid + j] = lo;
    }
}

// ---------------- persistent dataflow kernel ----------------
// 296 worker CTAs drain a slot-major queue of tiles with acquire/release
// dependency counters at (t, 32-row group) granularity.
__global__ __launch_bounds__(128)
void cfc_persist(const float* __restrict__ b0f1, const float* __restrict__ b0f2,
                 const float* __restrict__ b0ts,
                 const float* __restrict__ b1f1, const float* __restrict__ b1f2,
                 const float* __restrict__ b1ts,
                 const float* __restrict__ b2f1, const float* __restrict__ b2f2,
                 const float* __restrict__ b2ts)
{
    extern __shared__ __align__(16) uint32_t sm32[];
    __shared__ int s_item;
    const int tid = threadIdx.x;

    for (;;) {
        if (tid == 0) s_item = atomicAdd(&qhead, 1);
        __syncthreads();
        const int g = s_item;
        __syncthreads();
        if (g >= QTOT) break;

        const int s = g / QSLOT;
        const int r = g - s * QSLOT;
        int layer, t, bx, by;
        if (r < 256)      { layer = 0; t = s;     bx = r >> 4;         by = r & 15; }
        else if (r < 384) { layer = 1; t = s - 1; bx = (r - 256) >> 3; by = (r - 256) & 7; }
        else              { layer = 2; t = s - 2; bx = (r - 384) >> 1; by = (r - 384) & 1; }
        if (t < 0 || t >= KT) continue;

        const int pi = t & 1, po = pi ^ 1;

        if (layer == 0) {
            if (tid == 0) {
                if (t >= 1) wait_cnt(&cL0[(t - 1) * 16 + bx], 16);   // RAW h0 prev
                if (t >= 2) wait_cnt(&cL1[(t - 2) * 16 + bx], 8);    // WAR h0 slot reuse
            }
            __syncthreads();
            cfc_tile(sm32, bx, by,
                     Xh + (size_t)t * SENS, Xl + (size_t)t * SENS, KT * SENS, SENS,
                     h0h[pi], h0l[pi], H0,
                     W0h, W0l, b0f1, b0f2, b0ts,
                     C0, H0, h0h[po], h0l[po]);
            __threadfence();
            __syncthreads();
            if (tid == 0) release_cnt(&cL0[t * 16 + bx]);
        } else if (layer == 1) {
            if (tid == 0) {
                wait_cnt(&cL0[t * 16 + bx], 16);                     // RAW h0 new
                if (t >= 1) wait_cnt(&cL1[(t - 1) * 16 + bx], 8);    // RAW h1 prev
                if (t >= 2) wait_cnt(&cL2[(t - 2) * 16 + bx], 2);    // WAR h1 slot reuse
            }
            __syncthreads();
            cfc_tile(sm32, bx, by,
                     h0h[po], h0l[po], H0, H0,
                     h1h[pi], h1l[pi], H1,
                     W1h, W1l, b1f1, b1f2, b1ts,
                     C1, H1, h1h[po], h1l[po]);
            __threadfence();
            __syncthreads();
            if (tid == 0) release_cnt(&cL1[t * 16 + bx]);
        } else {
            if (tid == 0) {
                wait_cnt(&cL1[t * 16 + bx], 8);                      // RAW h1 new
                if (t >= 1) wait_cnt(&cL2[(t - 1) * 16 + bx], 2);    // RAW h2 prev (+WAR)
            }
            __syncthreads();
            cfc_tile(sm32, bx, by,
                     h1h[po], h1l[po], H1, H1,
                     h2h[pi], h2l[pi], H2,
                     W2h, W2l, b2f1, b2f2, b2ts,
                     C2, H2, h2h[po], h2l[po]);
            __threadfence();
            __syncthreads();
            if (tid == 0) release_cnt(&cL2[t * 16 + bx]);
        }
    }
}

// dynamic smem: 2 buf x 5120 u32 x 4 B = 40960 (>= Cs staging 32*100*4 = 12800)
#define SMF 40960

// merged time-scale bias: ts = ta_b + tb_b, computed at prep into a small buffer
__device__ float bts0[H0], bts1[H1], bts2[H2];
__global__ void prep_bts(const float* __restrict__ ta0, const float* __restrict__ tb0,
                         const float* __restrict__ ta1, const float* __restrict__ tb1,
                         const float* __restrict__ ta2, const float* __restrict__ tb2)
{
    int i = blockIdx.x * blockDim.x + threadIdx.x;
    if (i < H0) bts0[i] = ta0[i] + tb0[i];
    if (i < H1) bts1[i] = ta1[i] + tb1[i];
    if (i < H2) bts2[i] = ta2[i] + tb2[i];
}

// ---------------- host launcher ----------------
extern "C" void kernel_launch(void* const* d_in, const int* in_sizes, int n_in,
                              void* d_out, int out_size)
{
    const float* base = (const float*)d_in[0];
    const float* vis  = (const float*)d_in[1];
    const float* w[3][9];
    for (int li = 0; li < 3; li++)
        for (int q = 0; q < 9; q++)
            w[li][q] = (const float*)d_in[2 + li * 9 + q];

    __nv_bfloat16 *pXh, *pXl, *pW0h, *pW0l, *pW1h, *pW1l, *pW2h, *pW2l;
    __nv_bfloat16 *p0h, *p0l, *p1h, *p1l, *p2h, *p2l;
    float *pb0, *pb1, *pb2;
    cudaGetSymbolAddress((void**)&pXh, Xh);   cudaGetSymbolAddress((void**)&pXl, Xl);
    cudaGetSymbolAddress((void**)&pW0h, W0h); cudaGetSymbolAddress((void**)&pW0l, W0l);
    cudaGetSymbolAddress((void**)&pW1h, W1h); cudaGetSymbolAddress((void**)&pW1l, W1l);
    cudaGetSymbolAddress((void**)&pW2h, W2h); cudaGetSymbolAddress((void**)&pW2l, W2l);
    cudaGetSymbolAddress((void**)&p0h, h0h);  cudaGetSymbolAddress((void**)&p0l, h0l);
    cudaGetSymbolAddress((void**)&p1h, h1h);  cudaGetSymbolAddress((void**)&p1l, h1l);
    cudaGetSymbolAddress((void**)&p2h, h2h);  cudaGetSymbolAddress((void**)&p2l, h2l);
    cudaGetSymbolAddress((void**)&pb0, bts0);
    cudaGetSymbolAddress((void**)&pb1, bts1);
    cudaGetSymbolAddress((void**)&pb2, bts2);

    cudaFuncSetAttribute((const void*)cfc_persist,
                         cudaFuncAttributeMaxDynamicSharedMemorySize, SMF);

    // zero initial hidden states (ping buffer 0) + scheduler state
    cudaMemsetAsync(p0h, 0, (size_t)BQ * H0 * sizeof(__nv_bfloat16));
    cudaMemsetAsync(p0l, 0, (size_t)BQ * H0 * sizeof(__nv_bfloat16));
    cudaMemsetAsync(p1h, 0, (size_t)BQ * H1 * sizeof(__nv_bfloat16));
    cudaMemsetAsync(p1l, 0, (size_t)BQ * H1 * sizeof(__nv_bfloat16));
    cudaMemsetAsync(p2h, 0, (size_t)BQ * H2 * sizeof(__nv_bfloat16));
    cudaMemsetAsync(p2l, 0, (size_t)BQ * H2 * sizeof(__nv_bfloat16));
    prep_sched<<<(KT * 16 + 255) / 256, 256>>>();

    // prep
    {
        size_t n = (size_t)BQ * KT * SENS;
        prep_inputs_bf<<<(unsigned)((n + 255) / 256), 256>>>(base, vis, pXh, pXl);
    }
    prep_weights3<<<(H0 * C0 + 255) / 256, 256>>>(w[0][0], w[0][2], w[0][4], w[0][6], w[0][8], pW0h, pW0l, H0, C0);
    prep_weights3<<<(H1 * C1 + 255) / 256, 256>>>(w[1][0], w[1][2], w[1][4], w[1][6], w[1][8], pW1h, pW1l, H1, C1);
    prep_weights3<<<(H2 * C2 + 255) / 256, 256>>>(w[2][0], w[2][2], w[2][4], w[2][6], w[2][8], pW2h, pW2l, H2, C2);
    prep_bts<<<2, 256>>>(w[0][5], w[0][7], w[1][5], w[1][7], w[2][5], w[2][7]);

    // one persistent launch drains the whole 64-step dataflow
    cfc_persist<<<296, 128, SMF>>>(w[0][1], w[0][3], pb0,
                                   w[1][1], w[1][3], pb1,
                                   w[2][1], w[2][3], pb2);

    // final motor-layer state: L2(63) wrote slot 0
    extract_out<<<(BQ * H2 + 255) / 256, 256>>>(p2h, p2l, (float*)d_out, BQ * H2);
}

// round 16
// speedup vs baseline: 1.7219x; 1.1019x over previous
#include <cuda_runtime.h>
#include <cuda_bf16.h>
#include <math.h>
#include <stdint.h>

// Problem constants
#define BQ   512
#define KT   64
#define EBD  256
#define VFD  512
#define SENS 768
#define H0   512
#define H1   256
#define H2   64
#define C0   1280
#define C1   768
#define C2   320

// queue geometry:
//  prologue: Cin t=0..3            -> 1024 items
//  slot s (0..65): Cin(s+4) 256 | L0(s) 256 | L1(s-1) 128 | L2(s-2) 32 = 672
#define QSLOT 672
#define QTOT  (1024 + 66 * QSLOT)

// ---------------- device scratch (static, no allocation) ----------------
__device__ __align__(16) __nv_bfloat16 Xh[(size_t)BQ * KT * SENS];
__device__ __align__(16) __nv_bfloat16 Xl[(size_t)BQ * KT * SENS];
// Weights: [3*hid][cat] rows interleaved {ff1, ff2, ta+tb}, k contiguous.
__device__ __align__(16) __nv_bfloat16 W0h[(size_t)3 * H0 * C0];
__device__ __align__(16) __nv_bfloat16 W0l[(size_t)3 * H0 * C0];
__device__ __align__(16) __nv_bfloat16 W1h[(size_t)3 * H1 * C1];
__device__ __align__(16) __nv_bfloat16 W1l[(size_t)3 * H1 * C1];
__device__ __align__(16) __nv_bfloat16 W2h[(size_t)3 * H2 * C2];
__device__ __align__(16) __nv_bfloat16 W2l[(size_t)3 * H2 * C2];
__device__ __align__(16) __nv_bfloat16 h0h[2][BQ * H0];
__device__ __align__(16) __nv_bfloat16 h0l[2][BQ * H0];
__device__ __align__(16) __nv_bfloat16 h1h[2][BQ * H1];
__device__ __align__(16) __nv_bfloat16 h1l[2][BQ * H1];
__device__ __align__(16) __nv_bfloat16 h2h[2][BQ * H2];
__device__ __align__(16) __nv_bfloat16 h2l[2][BQ * H2];
// precomputed input-GEMM partials: Cin[t][512 rows][1536 cols] fp32 (201MB)
__device__ float CinG[(size_t)KT * BQ * 3 * H0];
// merged time-scale biases
__device__ float bts0[H0], bts1[H1], bts2[H2];
// scheduler state
__device__ int qhead;
__device__ int cCin[KT * 16];
__device__ int cL0[KT * 16];
__device__ int cL1[KT * 16];
__device__ int cL2[KT * 16];

// ---------------- helpers ----------------
__device__ __forceinline__ void bf16_split(float v, __nv_bfloat16& hi, __nv_bfloat16& lo)
{
    hi = __float2bfloat16(v);
    lo = __float2bfloat16(v - __bfloat162float(hi));
}

__device__ __forceinline__ void mma_bf16(float* d, const uint32_t* a, const uint32_t* b)
{
    asm volatile(
        "mma.sync.aligned.m16n8k16.row.col.f32.bf16.bf16.f32 "
        "{%0,%1,%2,%3}, {%4,%5,%6,%7}, {%8,%9}, {%0,%1,%2,%3};\n"
        : "+f"(d[0]), "+f"(d[1]), "+f"(d[2]), "+f"(d[3])
        : "r"(a[0]), "r"(a[1]), "r"(a[2]), "r"(a[3]),
          "r"(b[0]), "r"(b[1]));
}

__device__ __forceinline__ void cpa16(uint32_t* dst_smem, const void* src_gmem)
{
    uint32_t d = (uint32_t)__cvta_generic_to_shared(dst_smem);
    asm volatile("cp.async.cg.shared.global [%0], [%1], 16;\n" :: "r"(d), "l"(src_gmem));
}

#define LDSM4(r0, r1, r2, r3, a) \
    asm volatile("ldmatrix.sync.aligned.m8n8.x4.shared.b16 {%0,%1,%2,%3}, [%4];" \
                 : "=r"(r0), "=r"(r1), "=r"(r2), "=r"(r3) : "r"(a))

__device__ __forceinline__ void wait_cnt(const int* p, int target)
{
    for (;;) {
        int v;
        asm volatile("ld.acquire.gpu.global.b32 %0, [%1];" : "=r"(v) : "l"(p));
        if (v >= target) break;
        __nanosleep(128);
    }
}

__device__ __forceinline__ void release_cnt(int* p)
{
    asm volatile("red.release.gpu.global.add.s32 [%0], 1;" :: "l"(p) : "memory");
}

// ---------------- prep kernels ----------------
__global__ void prep_sched()
{
    int i = blockIdx.x * blockDim.x + threadIdx.x;
    if (i == 0) qhead = 0;
    if (i < KT * 16) { cCin[i] = 0; cL0[i] = 0; cL1[i] = 0; cL2[i] = 0; }
}

__global__ void prep_weights3(const float* __restrict__ ff1, const float* __restrict__ ff2,
                              const float* __restrict__ ta,  const float* __restrict__ tb,
                              const float* __restrict__ mask,
                              __nv_bfloat16* __restrict__ dh, __nv_bfloat16* __restrict__ dl,
                              int hid, int cat)
{
    int idx = blockIdx.x * blockDim.x + threadIdx.x;
    if (idx >= hid * cat) return;
    int j = idx / cat;
    int k = idx - j * cat;
    float m = mask[idx];
    float v[3] = { ff1[idx] * m, ff2[idx] * m, ta[idx] + tb[idx] };
    #pragma unroll
    for (int q = 0; q < 3; q++) {
        __nv_bfloat16 hi, lo;
        bf16_split(v[q], hi, lo);
        size_t o = (size_t)(3 * j + q) * cat + k;
        dh[o] = hi; dl[o] = lo;
    }
}

__global__ void prep_inputs_bf(const float* __restrict__ base, const float* __restrict__ vis,
                               __nv_bfloat16* __restrict__ xh, __nv_bfloat16* __restrict__ xl)
{
    size_t idx = (size_t)blockIdx.x * blockDim.x + threadIdx.x;
    if (idx >= (size_t)BQ * KT * SENS) return;
    size_t row = idx / SENS;
    int c = (int)(idx - row * SENS);
    float v = (c < EBD) ? base[row * EBD + c] : vis[row * VFD + (c - EBD)];
    __nv_bfloat16 hi, lo;
    bf16_split(v, hi, lo);
    xh[idx] = hi; xl[idx] = lo;
}

__global__ void prep_bts(const float* __restrict__ ta0, const float* __restrict__ tb0,
                         const float* __restrict__ ta1, const float* __restrict__ tb1,
                         const float* __restrict__ ta2, const float* __restrict__ tb2)
{
    int i = blockIdx.x * blockDim.x + threadIdx.x;
    if (i < H0) bts0[i] = ta0[i] + tb0[i];
    if (i < H1) bts1[i] = ta1[i] + tb1[i];
    if (i < H2) bts2[i] = ta2[i] + tb2[i];
}

__global__ void extract_out(const __nv_bfloat16* __restrict__ hh,
                            const __nv_bfloat16* __restrict__ hl,
                            float* __restrict__ out, int n)
{
    int i = blockIdx.x * blockDim.x + threadIdx.x;
    if (i < n) out[i] = __bfloat162float(hh[i]) + __bfloat162float(hl[i]);
}

// ---------------- shared GEMM core (3xBF16, m16n8k16, 32x96 tile) ----------------
// acc += A[32 rows, klen] @ W[klen, 96 cols]  (W rows k-contig at kstride).
// A rows from <=2 concatenated bf16-plane segments. 128 thr = 4 warps 2x2.
#define RS   20
#define APL  (32 * RS)
#define BPL  (96 * RS)
#define BUFSZ (2 * APL + 2 * BPL)
#define CS   100

__device__ __forceinline__ void gemm_acc(uint32_t* sm32, float acc[6][4],
                                         int rowBase, int colBase,
                                         const __nv_bfloat16* s0h, const __nv_bfloat16* s0l,
                                         int st0, int len0,
                                         const __nv_bfloat16* s1h, const __nv_bfloat16* s1l,
                                         int st1,
                                         const __nv_bfloat16* Wh, const __nv_bfloat16* Wl,
                                         int kstride, int klen)
{
    const int tid  = threadIdx.x;
    const int lane = tid & 31;
    const int wid  = tid >> 5;
    const int wm   = wid & 1;
    const int wn   = wid >> 1;

    const uint32_t smemB = (uint32_t)__cvta_generic_to_shared(sm32);
    const int aLaneRow = (lane & 7) + ((lane >> 3) & 1) * 8;
    const int aKoff    = ((lane >> 4) & 1) * 16;
    const int bLaneRow = (lane & 7) + ((lane >> 4) & 1) * 8;
    const int bKoff    = ((lane >> 3) & 1) * 16;
    const uint32_t aBaseOff = (uint32_t)((wm * 16 + aLaneRow) * (RS * 4) + aKoff);
    const uint32_t bBaseOff = (uint32_t)((wn * 48 + bLaneRow) * (RS * 4) + bKoff);

    auto load_tiles = [&](int k0, int buf) {
        const __nv_bfloat16 *shi, *slo; int ss, so;
        if (k0 < len0) { shi = s0h; slo = s0l; ss = st0; so = k0; }
        else           { shi = s1h; slo = s1l; ss = st1; so = k0 - len0; }
        uint32_t* bb = sm32 + buf * BUFSZ;
        {   // A: 32 rows x 4 chunks = 128
            int r = tid >> 2, c = tid & 3;
            size_t go = (size_t)(rowBase + r) * ss + so + c * 8;
            cpa16(bb + r * RS + c * 4, shi + go);
            cpa16(bb + APL + r * RS + c * 4, slo + go);
        }
        #pragma unroll
        for (int i = 0; i < 3; i++) {   // B: 96 rows x 4 chunks = 384
            int idx = tid + i * 128;
            int r = idx >> 2, c = idx & 3;
            size_t go = (size_t)(colBase + r) * kstride + k0 + c * 8;
            cpa16(bb + 2 * APL + r * RS + c * 4, Wh + go);
            cpa16(bb + 2 * APL + BPL + r * RS + c * 4, Wl + go);
        }
        asm volatile("cp.async.commit_group;\n");
    };

    load_tiles(0, 0);

    const int ntile = klen / 32;
    int buf = 0;
    for (int it = 0; it < ntile; it++, buf ^= 1) {
        if (it + 1 < ntile) {
            load_tiles((it + 1) * 32, buf ^ 1);
            asm volatile("cp.async.wait_group 1;\n");
        } else {
            asm volatile("cp.async.wait_group 0;\n");
        }
        __syncthreads();

        const uint32_t bufB = smemB + (uint32_t)(buf * BUFSZ) * 4;
        const uint32_t aHi = bufB + aBaseOff;
        const uint32_t aLo = bufB + (uint32_t)APL * 4 + aBaseOff;
        const uint32_t bHi = bufB + (uint32_t)(2 * APL) * 4 + bBaseOff;
        const uint32_t bLo = bufB + (uint32_t)(2 * APL + BPL) * 4 + bBaseOff;

        #pragma unroll
        for (int k16 = 0; k16 < 2; k16++) {
            const uint32_t ko = (uint32_t)(k16 * 32);
            uint32_t ah[4], al[4];
            LDSM4(ah[0], ah[1], ah[2], ah[3], aHi + ko);
            LDSM4(al[0], al[1], al[2], al[3], aLo + ko);
            uint32_t bh[6][2], bl[6][2];
            #pragma unroll
            for (int p = 0; p < 3; p++) {
                LDSM4(bh[2 * p][0], bh[2 * p][1], bh[2 * p + 1][0], bh[2 * p + 1][1],
                      bHi + p * 16 * (RS * 4) + ko);
                LDSM4(bl[2 * p][0], bl[2 * p][1], bl[2 * p + 1][0], bl[2 * p + 1][1],
                      bLo + p * 16 * (RS * 4) + ko);
            }
            #pragma unroll
            for (int nt = 0; nt < 6; nt++) mma_bf16(acc[nt], ah, bh[nt]);
            #pragma unroll
            for (int nt = 0; nt < 6; nt++) mma_bf16(acc[nt], ah, bl[nt]);
            #pragma unroll
            for (int nt = 0; nt < 6; nt++) mma_bf16(acc[nt], al, bh[nt]);
        }
        __syncthreads();
    }
}

// stage acc fragments into Cs (fp32, 32 x 96, stride CS)
__device__ __forceinline__ void stage_acc(uint32_t* sm32, float acc[6][4])
{
    const int tid  = threadIdx.x;
    const int lane = tid & 31;
    const int wid  = tid >> 5;
    const int wm   = wid & 1;
    const int wn   = wid >> 1;
    const int g    = lane >> 2;
    const int tc   = lane & 3;
    float* Cs = reinterpret_cast<float*>(sm32);
    const int r0 = wm * 16 + g;
    const int cb = wn * 48 + 2 * tc;
    #pragma unroll
    for (int nt = 0; nt < 6; nt++) {
        const int c = cb + nt * 8;
        *reinterpret_cast<float2*>(&Cs[r0 * CS + c])       = make_float2(acc[nt][0], acc[nt][1]);
        *reinterpret_cast<float2*>(&Cs[(r0 + 8) * CS + c]) = make_float2(acc[nt][2], acc[nt][3]);
    }
}

// ---------------- Cin tile: pure GEMM, fp32 store ----------------
__device__ void cin_tile(uint32_t* sm32, int t, int bx, int by)
{
    float acc[6][4];
    #pragma unroll
    for (int q = 0; q < 6; q++)
        #pragma unroll
        for (int z = 0; z < 4; z++) acc[q][z] = 0.0f;

    const int rowBase = bx * 32;
    const int colBase = by * 96;
    gemm_acc(sm32, acc, rowBase, colBase,
             Xh + (size_t)t * SENS, Xl + (size_t)t * SENS, KT * SENS, SENS,
             Xh + (size_t)t * SENS, Xl + (size_t)t * SENS, KT * SENS,
             W0h, W0l, C0, SENS);

    stage_acc(sm32, acc);
    __syncthreads();

    const float* Cs = reinterpret_cast<const float*>(sm32);
    float* dst = CinG + (size_t)t * BQ * 3 * H0;
    const int tid = threadIdx.x;
    #pragma unroll
    for (int i = 0; i < 6; i++) {
        int o = tid + i * 128;           // 768 float4s
        int r = o / 24, c4 = o % 24;
        float4 v = make_float4(Cs[r * CS + c4 * 4 + 0], Cs[r * CS + c4 * 4 + 1],
                               Cs[r * CS + c4 * 4 + 2], Cs[r * CS + c4 * 4 + 3]);
        *reinterpret_cast<float4*>(&dst[(size_t)(rowBase + r) * (3 * H0) + colBase + c4 * 4]) = v;
    }
}

// ---------------- CfC tile: GEMM + epilogue (optional Cin partial add) ----------------
__device__ void cfc_tile(uint32_t* sm32, int bx, int by,
                         const __nv_bfloat16* s0h, const __nv_bfloat16* s0l, int st0, int len0,
                         const __nv_bfloat16* s1h, const __nv_bfloat16* s1l, int st1,
                         const __nv_bfloat16* Wh, const __nv_bfloat16* Wl,
                         int kstride, int klen,
                         const float* __restrict__ bff1, const float* __restrict__ bff2,
                         const float* __restrict__ bts,
                         const float* __restrict__ cinp,   // nullptr or Cin[t] base
                         int hid,
                         __nv_bfloat16* __restrict__ oh, __nv_bfloat16* __restrict__ ol)
{
    float acc[6][4];
    #pragma unroll
    for (int q = 0; q < 6; q++)
        #pragma unroll
        for (int z = 0; z < 4; z++) acc[q][z] = 0.0f;

    const int rowBase = bx * 32;
    const int colBase = by * 96;
    gemm_acc(sm32, acc, rowBase, colBase, s0h, s0l, st0, len0, s1h, s1l, st1,
             Wh, Wl, kstride, klen);

    stage_acc(sm32, acc);
    __syncthreads();

    const float* Cs = reinterpret_cast<const float*>(sm32);
    const int jBase = colBase / 3;
    const int tid = threadIdx.x;
    #pragma unroll
    for (int i = 0; i < 8; i++) {
        int o  = tid + i * 128;          // 0..1023
        int r  = o >> 5;                 // 0..31
        int jj = o & 31;
        float c0 = Cs[r * CS + 3 * jj + 0];
        float c1 = Cs[r * CS + 3 * jj + 1];
        float c2 = Cs[r * CS + 3 * jj + 2];
        if (cinp) {
            const float* cp = cinp + (size_t)(rowBase + r) * (3 * H0) + colBase + 3 * jj;
            c0 += __ldg(cp + 0);
            c1 += __ldg(cp + 1);
            c2 += __ldg(cp + 2);
        }
        int j = jBase + jj;
        float f1 = tanhf(c0 + bff1[j]);
        float f2 = tanhf(c1 + bff2[j]);
        float ti = 1.0f / (1.0f + expf(-(c2 + bts[j])));
        float v  = f1 + ti * (f2 - f1);
        __nv_bfloat16 hi, lo; bf16_split(v, hi, lo);
        oh[(size_t)(rowBase + r) * hid + j] = hi;
        ol[(size_t)(rowBase + r) * hid + j] = lo;
    }
}

// ---------------- persistent dataflow kernel ----------------
// 592 worker CTAs drain a queue mixing recurrence tiles with independent
// input-GEMM (Cin) filler tiles; acquire/release counters at (t, 32-row) grain.
__global__ __launch_bounds__(128)
void cfc_persist(const float* __restrict__ b0f1, const float* __restrict__ b0f2,
                 const float* __restrict__ b1f1, const float* __restrict__ b1f2,
                 const float* __restrict__ b2f1, const float* __restrict__ b2f2)
{
    extern __shared__ __align__(16) uint32_t sm32[];
    __shared__ int s_item;
    const int tid = threadIdx.x;

    for (;;) {
        if (tid == 0) s_item = atomicAdd(&qhead, 1);
        __syncthreads();
        const int g = s_item;
        __syncthreads();
        if (g >= QTOT) break;

        int layer, t, bx, by;
        if (g < 1024) {
            layer = 3; t = g >> 8;
            int r = g & 255; bx = r >> 4; by = r & 15;
        } else {
            int G = g - 1024;
            int s = G / QSLOT;
            int r = G - s * QSLOT;
            if (r < 256)      { layer = 3; t = s + 4; bx = r >> 4;         by = r & 15; }
            else if (r < 512) { layer = 0; t = s;     bx = (r - 256) >> 4; by = (r - 256) & 15; }
            else if (r < 640) { layer = 1; t = s - 1; bx = (r - 512) >> 3; by = (r - 512) & 7; }
            else              { layer = 2; t = s - 2; bx = (r - 640) >> 1; by = (r - 640) & 1; }
        }
        if (t < 0 || t >= KT) continue;

        const int pi = t & 1, po = pi ^ 1;

        if (layer == 3) {
            cin_tile(sm32, t, bx, by);
            __threadfence();
            __syncthreads();
            if (tid == 0) release_cnt(&cCin[t * 16 + bx]);
        } else if (layer == 0) {
            if (tid == 0) {
                wait_cnt(&cCin[t * 16 + bx], 16);                    // input partial ready
                if (t >= 1) wait_cnt(&cL0[(t - 1) * 16 + bx], 16);   // RAW h0 prev
                if (t >= 2) wait_cnt(&cL1[(t - 2) * 16 + bx], 8);    // WAR h0 slot reuse
            }
            __syncthreads();
            cfc_tile(sm32, bx, by,
                     h0h[pi], h0l[pi], H0, H0,
                     h0h[pi], h0l[pi], H0,
                     W0h + SENS, W0l + SENS, C0, H0,
                     b0f1, b0f2, bts0,
                     CinG + (size_t)t * BQ * 3 * H0,
                     H0, h0h[po], h0l[po]);
            __threadfence();
            __syncthreads();
            if (tid == 0) release_cnt(&cL0[t * 16 + bx]);
        } else if (layer == 1) {
            if (tid == 0) {
                wait_cnt(&cL0[t * 16 + bx], 16);                     // RAW h0 new
                if (t >= 1) wait_cnt(&cL1[(t - 1) * 16 + bx], 8);    // RAW h1 prev
                if (t >= 2) wait_cnt(&cL2[(t - 2) * 16 + bx], 2);    // WAR h1 slot reuse
            }
            __syncthreads();
            cfc_tile(sm32, bx, by,
                     h0h[po], h0l[po], H0, H0,
                     h1h[pi], h1l[pi], H1,
                     W1h, W1l, C1, C1,
                     b1f1, b1f2, bts1,
                     (const float*)nullptr,
                     H1, h1h[po], h1l[po]);
            __threadfence();
            __syncthreads();
            if (tid == 0) release_cnt(&cL1[t * 16 + bx]);
        } else {
            if (tid == 0) {
                wait_cnt(&cL1[t * 16 + bx], 8);                      // RAW h1 new
                if (t >= 1) wait_cnt(&cL2[(t - 1) * 16 + bx], 2);    // RAW h2 prev (+WAR)
            }
            __syncthreads();
            cfc_tile(sm32, bx, by,
                     h1h[po], h1l[po], H1, H1,
                     h2h[pi], h2l[pi], H2,
                     W2h, W2l, C2, C2,
                     b2f1, b2f2, bts2,
                     (const float*)nullptr,
                     H2, h2h[po], h2l[po]);
            __threadfence();
            __syncthreads();
            if (tid == 0) release_cnt(&cL2[t * 16 + bx]);
        }
    }
}

// dynamic smem: 2 buf x 5120 u32 x 4 B = 40960 (>= Cs staging 32*100*4 = 12800)
#define SMF 40960

// ---------------- host launcher ----------------
extern "C" void kernel_launch(void* const* d_in, const int* in_sizes, int n_in,
                              void* d_out, int out_size)
{
    const float* base = (const float*)d_in[0];
    const float* vis  = (const float*)d_in[1];
    const float* w[3][9];
    for (int li = 0; li < 3; li++)
        for (int q = 0; q < 9; q++)
            w[li][q] = (const float*)d_in[2 + li * 9 + q];

    __nv_bfloat16 *pXh, *pXl, *pW0h, *pW0l, *pW1h, *pW1l, *pW2h, *pW2l;
    __nv_bfloat16 *p0h, *p0l, *p1h, *p1l, *p2h, *p2l;
    cudaGetSymbolAddress((void**)&pXh, Xh);   cudaGetSymbolAddress((void**)&pXl, Xl);
    cudaGetSymbolAddress((void**)&pW0h, W0h); cudaGetSymbolAddress((void**)&pW0l, W0l);
    cudaGetSymbolAddress((void**)&pW1h, W1h); cudaGetSymbolAddress((void**)&pW1l, W1l);
    cudaGetSymbolAddress((void**)&pW2h, W2h); cudaGetSymbolAddress((void**)&pW2l, W2l);
    cudaGetSymbolAddress((void**)&p0h, h0h);  cudaGetSymbolAddress((void**)&p0l, h0l);
    cudaGetSymbolAddress((void**)&p1h, h1h);  cudaGetSymbolAddress((void**)&p1l, h1l);
    cudaGetSymbolAddress((void**)&p2h, h2h);  cudaGetSymbolAddress((void**)&p2l, h2l);

    cudaFuncSetAttribute((const void*)cfc_persist,
                         cudaFuncAttributeMaxDynamicSharedMemorySize, SMF);

    // zero initial hidden states (ping buffer 0) + scheduler state
    cudaMemsetAsync(p0h, 0, (size_t)BQ * H0 * sizeof(__nv_bfloat16));
    cudaMemsetAsync(p0l, 0, (size_t)BQ * H0 * sizeof(__nv_bfloat16));
    cudaMemsetAsync(p1h, 0, (size_t)BQ * H1 * sizeof(__nv_bfloat16));
    cudaMemsetAsync(p1l, 0, (size_t)BQ * H1 * sizeof(__nv_bfloat16));
    cudaMemsetAsync(p2h, 0, (size_t)BQ * H2 * sizeof(__nv_bfloat16));
    cudaMemsetAsync(p2l, 0, (size_t)BQ * H2 * sizeof(__nv_bfloat16));
    prep_sched<<<(KT * 16 + 255) / 256, 256>>>();

    // prep
    {
        size_t n = (size_t)BQ * KT * SENS;
        prep_inputs_bf<<<(unsigned)((n + 255) / 256), 256>>>(base, vis, pXh, pXl);
    }
    prep_weights3<<<(H0 * C0 + 255) / 256, 256>>>(w[0][0], w[0][2], w[0][4], w[0][6], w[0][8], pW0h, pW0l, H0, C0);
    prep_weights3<<<(H1 * C1 + 255) / 256, 256>>>(w[1][0], w[1][2], w[1][4], w[1][6], w[1][8], pW1h, pW1l, H1, C1);
    prep_weights3<<<(H2 * C2 + 255) / 256, 256>>>(w[2][0], w[2][2], w[2][4], w[2][6], w[2][8], pW2h, pW2l, H2, C2);
    prep_bts<<<2, 256>>>(w[0][5], w[0][7], w[1][5], w[1][7], w[2][5], w[2][7]);

    // one persistent launch: recurrence tiles + input-GEMM filler tiles
    cfc_persist<<<592, 128, SMF>>>(w[0][1], w[0][3],
                                   w[1][1], w[1][3],
                                   w[2][1], w[2][3]);

    // final motor-layer state: L2(63) wrote slot 0
    extract_out<<<(BQ * H2 + 255) / 256, 256>>>(p2h, p2l, (float*)d_out, BQ * H2);
}